// round 16
// baseline (speedup 1.0000x reference)
#include <cuda_runtime.h>
#include <cuda_fp16.h>
#include <cstdint>

#define NN 8192
#define FF 128
#define NEG 0.2f
#define KC 128                    // K-chunk (columns per iteration)
#define NSPLIT 4
#define NCHS (NN / KC / NSPLIT)   // 16 chunks per split
#define BROW 272                  // smem row pitch bytes (128 halves + 8 pad)

// ----------------------------- device scratch ------------------------------
__device__ float g_xp[(size_t)NN * FF];       // x' = x@W + b (fp32)
__device__ __half g_xht[(size_t)FF * NN];     // x'^T in f16 [f][j]
__device__ float g_ssrc[NN];
__device__ float g_sdst[NN];
__device__ float g_fac[3 * NN];               // ne | ne2 | nb
__device__ unsigned g_maxbits;
__device__ float g_pnum[(size_t)NSPLIT * NN * FF];
__device__ float g_pden[NSPLIT * NN];

// ----------------------------- helpers -------------------------------------
__device__ __forceinline__ uint32_t s2u(const void* p) {
    uint32_t a;
    asm("{ .reg .u64 t; cvta.to.shared.u64 t, %1; cvt.u32.u64 %0, t; }" : "=r"(a) : "l"(p));
    return a;
}
#define LDSM4(d0, d1, d2, d3, addr)                                           \
    asm volatile("ldmatrix.sync.aligned.m8n8.x4.shared.b16 {%0,%1,%2,%3}, [%4];" \
                 : "=r"(d0), "=r"(d1), "=r"(d2), "=r"(d3) : "r"(addr))
#define MMA16816(d, A0, A1, A2, A3, B0, B1)                                   \
    asm volatile(                                                             \
        "mma.sync.aligned.m16n8k16.row.col.f32.f16.f16.f32 "                  \
        "{%0,%1,%2,%3}, {%4,%5,%6,%7}, {%8,%9}, {%0,%1,%2,%3};"               \
        : "+f"((d)[0]), "+f"((d)[1]), "+f"((d)[2]), "+f"((d)[3])              \
        : "r"(A0), "r"(A1), "r"(A2), "r"(A3), "r"(B0), "r"(B1))
#define CP16(dst, src)                                                        \
    asm volatile("cp.async.ca.shared.global [%0], [%1], 16;" :: "r"(dst), "l"(src) : "memory")
#define CPCOMMIT() asm volatile("cp.async.commit_group;" ::: "memory")
#define CPWAIT0()  asm volatile("cp.async.wait_group 0;" ::: "memory")

// ----------------------------- K1: x' = x@W + b (+init) --------------------
__global__ void k_gemm(const float* __restrict__ x, const float* __restrict__ w,
                       const float* __restrict__ bias) {
    __shared__ float ws[64][128];
    __shared__ float xs[32][64];
    const int tid = threadIdx.x;
    const int row0 = blockIdx.x * 32;
    if (blockIdx.x == 0 && tid == 0) g_maxbits = 0u;
    const int c = tid & 127;
    const int rr = tid >> 7;
    float acc[16];
#pragma unroll
    for (int q = 0; q < 16; ++q) acc[q] = 0.f;
    for (int kb = 0; kb < 128; kb += 64) {
        for (int t = tid; t < 64 * 128; t += 256)
            ws[t >> 7][t & 127] = w[(kb + (t >> 7)) * 128 + (t & 127)];
        for (int t = tid; t < 32 * 64; t += 256)
            xs[t >> 6][t & 63] = x[(size_t)(row0 + (t >> 6)) * 128 + kb + (t & 63)];
        __syncthreads();
#pragma unroll 4
        for (int kk = 0; kk < 64; ++kk) {
            float wv = ws[kk][c];
#pragma unroll
            for (int q = 0; q < 16; ++q) acc[q] += xs[rr * 16 + q][kk] * wv;
        }
        __syncthreads();
    }
    const float b = bias[c];
#pragma unroll
    for (int q = 0; q < 16; ++q)
        g_xp[(size_t)(row0 + rr * 16 + q) * 128 + c] = acc[q] + b;
}

// ----------------------------- K2: scores ----------------------------------
__global__ void k_score(const float* __restrict__ phi) {
    const int warp = threadIdx.x >> 5, lane = threadIdx.x & 31;
    const int i = blockIdx.x * 8 + warp;
    const float4* xr = (const float4*)(g_xp + (size_t)i * FF);
    const float4* pl = (const float4*)phi;
    const float4* ph = (const float4*)(phi + FF);
    float4 xv = xr[lane], a = pl[lane], b = ph[lane];
    float s1 = xv.x * a.x + xv.y * a.y + xv.z * a.z + xv.w * a.w;
    float s2 = xv.x * b.x + xv.y * b.y + xv.z * b.z + xv.w * b.w;
#pragma unroll
    for (int o = 16; o; o >>= 1) {
        s1 += __shfl_xor_sync(0xffffffffu, s1, o);
        s2 += __shfl_xor_sync(0xffffffffu, s2, o);
    }
    if (lane == 0) {
        g_ssrc[i] = s1;
        g_sdst[i] = s2;
        unsigned bits = __float_as_uint(s2);
        unsigned enc = bits ^ ((bits >> 31) ? 0xFFFFFFFFu : 0x80000000u);
        atomicMax(&g_maxbits, enc);
    }
}

// ----------------------------- K2b: factors + X'^T f16 (merged) ------------
__global__ void k_prep() {
    __shared__ float t[32][33];
    const int jb = blockIdx.x * 32, fb = blockIdx.y * 32;
    const int tx = threadIdx.x, ty = threadIdx.y;     // (32,8)
#pragma unroll
    for (int q = 0; q < 4; ++q)
        t[ty + q * 8][tx] = g_xp[(size_t)(jb + ty + q * 8) * 128 + fb + tx];
    __syncthreads();
#pragma unroll
    for (int q = 0; q < 4; ++q)
        g_xht[(size_t)(fb + ty + q * 8) * NN + jb + tx] = __float2half_rn(t[tx][ty + q * 8]);

    if (blockIdx.y == 0 && blockIdx.x < 32) {
        const int i = blockIdx.x * 256 + ty * 32 + tx;
        const unsigned u = g_maxbits;
        const float dmax = __uint_as_float(u ^ ((u >> 31) ? 0x80000000u : 0xFFFFFFFFu));
        const float d = g_sdst[i] - dmax;     // <= 0
        g_fac[i] = expf(d);
        g_fac[NN + i] = expf(NEG * d);
        g_fac[2 * NN + i] = d;
    }
}

// ----------------------------- K3: HMMA attention (split-K) ----------------
// SMEM: P0 | P1 (64 x 128 f16 each) | B0 | B1 (128 x 128 f16 each) | row consts
#define P0_OFF 0
#define P1_OFF 17408
#define B0_OFF 34816
#define B1_OFF 69632
#define RC_OFF 104448
#define SMEM_TOTAL (RC_OFF + 3 * 64 * 4)

__global__ void __launch_bounds__(256, 2)
k_attn_hmma(const float* __restrict__ adj) {
    extern __shared__ __align__(16) char smem[];
    float* sA  = (float*)(smem + RC_OFF);
    float* sE  = sA + 64;
    float* sE2 = sA + 128;

    const int tid = threadIdx.x;
    const int wid = tid >> 5, lane = tid & 31;
    const int i0 = blockIdx.x * 64;
    const int sp = blockIdx.y;
    const int rowbase = i0 + 8 * wid;          // producer rows for this warp

    char* Pw[2] = {smem + P0_OFF, smem + P1_OFF};
    const uint32_t uP[2] = {s2u(smem + P0_OFF), s2u(smem + P1_OFF)};
    const uint32_t uB[2] = {s2u(smem + B0_OFF), s2u(smem + B1_OFF)};

    // ---- row constants ----
    if (tid < 64) {
        const int i = i0 + tid;
        const unsigned u = g_maxbits;
        const float dmax = __uint_as_float(u ^ ((u >> 31) ? 0x80000000u : 0xFFFFFFFFu));
        const float ra1 = g_ssrc[i] + dmax;
        const float mvv = ra1 > 0.f ? ra1 : NEG * ra1;
        sA[tid] = ra1;
        sE[tid] = expf(ra1 - mvv);
        sE2[tid] = expf(NEG * ra1 - mvv);
    }

    // ---- consumer fragment addressing (m32n32 per warp: 2r x 4n grid) ----
    const int r0 = (wid & 1) * 32, n0 = (wid >> 1) * 32;
    const uint32_t aOff0 = (uint32_t)((r0 + (lane & 15)) * BROW + (lane >> 4) * 16);
    const uint32_t aOff1 = aOff0 + 16 * BROW;
    const uint32_t bOff = (uint32_t)((n0 + ((lane >> 4) << 3) + (lane & 7)) * BROW +
                                     ((lane >> 3) & 1) * 16);
    float acc[2][4][4];
#pragma unroll
    for (int mt = 0; mt < 2; ++mt)
#pragma unroll
        for (int nt = 0; nt < 4; ++nt)
#pragma unroll
            for (int k = 0; k < 4; ++k) acc[mt][nt][k] = 0.f;
    float dacc[8];
#pragma unroll
    for (int rr = 0; rr < 8; ++rr) dacc[rr] = 0.f;

    // ---- B cp.async addressing ----
    const int bf0 = 16 * wid + (lane >> 4);
    const int bc16 = (lane & 15) * 16;

    // ---- prologue: B(0) + adj/fac prefetch(0) ----
    {
        const int j0 = sp * NCHS * KC;
#pragma unroll
        for (int p = 0; p < 8; ++p) {
            const int f = bf0 + 2 * p;
            CP16(uB[0] + f * BROW + bc16,
                 (const char*)g_xht + ((size_t)f * NN + j0) * 2 + bc16);
        }
        CPCOMMIT();
    }
    float4 av[8], fne, fne2, fnb;
    {
        const int j0 = sp * NCHS * KC;
#pragma unroll
        for (int rr = 0; rr < 8; ++rr)
            av[rr] = __ldg((const float4*)(adj + (size_t)(rowbase + rr) * NN + j0) + lane);
        fne  = __ldg((const float4*)(g_fac + j0) + lane);
        fne2 = __ldg((const float4*)(g_fac + NN + j0) + lane);
        fnb  = __ldg((const float4*)(g_fac + 2 * NN + j0) + lane);
    }
    CPWAIT0();
    __syncthreads();            // row consts + B0 visible

    // ---- build P(0) into P0 ----
    {
        const int j0 = sp * NCHS * KC;
        const int jl = j0 + lane * 4;
#pragma unroll
        for (int rr = 0; rr < 8; ++rr) {
            const int irow = rowbase + rr;
            const float ra1 = sA[8 * wid + rr];
            const float er = sE[8 * wid + rr], er2 = sE2[8 * wid + rr];
            float p0 = (ra1 + fnb.x) > 0.f ? er * fne.x : er2 * fne2.x;
            float p1 = (ra1 + fnb.y) > 0.f ? er * fne.y : er2 * fne2.y;
            float p2 = (ra1 + fnb.z) > 0.f ? er * fne.z : er2 * fne2.z;
            float p3 = (ra1 + fnb.w) > 0.f ? er * fne.w : er2 * fne2.w;
            p0 = (av[rr].x > 0.f || jl + 0 == irow) ? p0 : 0.f;
            p1 = (av[rr].y > 0.f || jl + 1 == irow) ? p1 : 0.f;
            p2 = (av[rr].z > 0.f || jl + 2 == irow) ? p2 : 0.f;
            p3 = (av[rr].w > 0.f || jl + 3 == irow) ? p3 : 0.f;
            __half2 h01 = __floats2half2_rn(p0, p1);
            __half2 h23 = __floats2half2_rn(p2, p3);
            const float2 f01 = __half22float2(h01);
            const float2 f23 = __half22float2(h23);
            dacc[rr] += (f01.x + f01.y) + (f23.x + f23.y);
            uint2 st;
            st.x = *reinterpret_cast<uint32_t*>(&h01);
            st.y = *reinterpret_cast<uint32_t*>(&h23);
            *(uint2*)(Pw[0] + (8 * wid + rr) * BROW + lane * 8) = st;
        }
    }
    __syncthreads();            // P0 visible

    // ---- main loop: ONE barrier per chunk (P and B double-buffered) ----
    for (int cs = 0; cs < NCHS; ++cs) {
        const int buf = cs & 1;
        const bool more = (cs + 1 < NCHS);

        // prefetch chunk cs+1 (B -> smem[buf^1], adj/fac -> regs)
        if (more) {
            const int j0n = (sp * NCHS + cs + 1) * KC;
#pragma unroll
            for (int p = 0; p < 8; ++p) {
                const int f = bf0 + 2 * p;
                CP16(uB[buf ^ 1] + f * BROW + bc16,
                     (const char*)g_xht + ((size_t)f * NN + j0n) * 2 + bc16);
            }
            CPCOMMIT();
#pragma unroll
            for (int rr = 0; rr < 8; ++rr)
                av[rr] = __ldg((const float4*)(adj + (size_t)(rowbase + rr) * NN + j0n) + lane);
            fne  = __ldg((const float4*)(g_fac + j0n) + lane);
            fne2 = __ldg((const float4*)(g_fac + NN + j0n) + lane);
            fnb  = __ldg((const float4*)(g_fac + 2 * NN + j0n) + lane);
        }

        // --- mma on chunk cs (P[buf], B[buf]) ---
        const uint32_t uPc = uP[buf], uBc = uB[buf];
#pragma unroll
        for (int ks = 0; ks < 8; ++ks) {
            const uint32_t k2 = ks * 32;
            uint32_t A0, A1, A2, A3, A4, A5, A6, A7;
            LDSM4(A0, A1, A2, A3, uPc + aOff0 + k2);
            LDSM4(A4, A5, A6, A7, uPc + aOff1 + k2);
#pragma unroll
            for (int ng = 0; ng < 2; ++ng) {
                uint32_t B0, B1, B2, B3;
                LDSM4(B0, B1, B2, B3, uBc + bOff + ng * (16 * BROW) + k2);
                MMA16816(acc[0][2 * ng],     A0, A1, A2, A3, B0, B1);
                MMA16816(acc[0][2 * ng + 1], A0, A1, A2, A3, B2, B3);
                MMA16816(acc[1][2 * ng],     A4, A5, A6, A7, B0, B1);
                MMA16816(acc[1][2 * ng + 1], A4, A5, A6, A7, B2, B3);
            }
        }

        // --- build P(cs+1) into P[buf^1] ---
        if (more) {
            const int j0n = (sp * NCHS + cs + 1) * KC;
            const int jl = j0n + lane * 4;
#pragma unroll
            for (int rr = 0; rr < 8; ++rr) {
                const int irow = rowbase + rr;
                const float ra1 = sA[8 * wid + rr];
                const float er = sE[8 * wid + rr], er2 = sE2[8 * wid + rr];
                float p0 = (ra1 + fnb.x) > 0.f ? er * fne.x : er2 * fne2.x;
                float p1 = (ra1 + fnb.y) > 0.f ? er * fne.y : er2 * fne2.y;
                float p2 = (ra1 + fnb.z) > 0.f ? er * fne.z : er2 * fne2.z;
                float p3 = (ra1 + fnb.w) > 0.f ? er * fne.w : er2 * fne2.w;
                p0 = (av[rr].x > 0.f || jl + 0 == irow) ? p0 : 0.f;
                p1 = (av[rr].y > 0.f || jl + 1 == irow) ? p1 : 0.f;
                p2 = (av[rr].z > 0.f || jl + 2 == irow) ? p2 : 0.f;
                p3 = (av[rr].w > 0.f || jl + 3 == irow) ? p3 : 0.f;
                __half2 h01 = __floats2half2_rn(p0, p1);
                __half2 h23 = __floats2half2_rn(p2, p3);
                const float2 f01 = __half22float2(h01);
                const float2 f23 = __half22float2(h23);
                dacc[rr] += (f01.x + f01.y) + (f23.x + f23.y);
                uint2 st;
                st.x = *reinterpret_cast<uint32_t*>(&h01);
                st.y = *reinterpret_cast<uint32_t*>(&h23);
                *(uint2*)(Pw[buf ^ 1] + (8 * wid + rr) * BROW + lane * 8) = st;
            }
        }

        CPWAIT0();
        __syncthreads();        // P(cs+1) + B(cs+1) visible; mma(cs) drained
    }

    // ---- denominator partials (warp-reduce, fixed order) ----
#pragma unroll
    for (int rr = 0; rr < 8; ++rr) {
        float v = dacc[rr];
#pragma unroll
        for (int o = 16; o; o >>= 1) v += __shfl_xor_sync(0xffffffffu, v, o);
        if (lane == 0) g_pden[sp * NN + rowbase + rr] = v;
    }

    // ---- numerator partials ----
    float* pnum = g_pnum + (size_t)sp * NN * FF;
    const int gg = lane >> 2, cc = lane & 3;
#pragma unroll
    for (int mt = 0; mt < 2; ++mt) {
        const int ra = r0 + mt * 16 + gg, rb = ra + 8;
#pragma unroll
        for (int nt = 0; nt < 4; ++nt) {
            const int col = n0 + nt * 8 + 2 * cc;
            *(float2*)(pnum + (size_t)(i0 + ra) * FF + col) =
                make_float2(acc[mt][nt][0], acc[mt][nt][1]);
            *(float2*)(pnum + (size_t)(i0 + rb) * FF + col) =
                make_float2(acc[mt][nt][2], acc[mt][nt][3]);
        }
    }
}

// ----------------------------- K4: split-K combine -------------------------
__global__ void k_combine(float* __restrict__ out) {
    const int idx = blockIdx.x * 256 + threadIdx.x;
    const int i = idx >> 7;
    const float den = (g_pden[i] + g_pden[NN + i]) +
                      (g_pden[2 * NN + i] + g_pden[3 * NN + i]);
    const size_t o = (size_t)idx;
    const float num = (g_pnum[o] + g_pnum[(size_t)NN * FF + o]) +
                      (g_pnum[2 * (size_t)NN * FF + o] + g_pnum[3 * (size_t)NN * FF + o]);
    out[o] = num / den;
}

// ---------------------------------------------------------------------------
extern "C" void kernel_launch(void* const* d_in, const int* in_sizes, int n_in,
                              void* d_out, int out_size) {
    const float* adj  = (const float*)d_in[0];
    const float* x    = (const float*)d_in[1];
    const float* w    = (const float*)d_in[2];
    const float* bias = (const float*)d_in[3];
    const float* phi  = (const float*)d_in[4];
    float* out = (float*)d_out;

    cudaFuncSetAttribute(k_attn_hmma, cudaFuncAttributeMaxDynamicSharedMemorySize,
                         SMEM_TOTAL);

    k_gemm<<<NN / 32, 256>>>(x, w, bias);
    k_score<<<NN / 8, 256>>>(phi);
    {
        dim3 b(32, 8), g(NN / 32, FF / 32);
        k_prep<<<g, b>>>();
    }
    {
        dim3 g(NN / 64, NSPLIT);
        k_attn_hmma<<<g, 256, SMEM_TOTAL>>>(adj);
    }
    k_combine<<<NN * FF / 256, 256>>>(out);
}